// round 16
// baseline (speedup 1.0000x reference)
#include <cuda_runtime.h>
#include <cuda_fp16.h>
#include <cstdint>

// ---------------------------------------------------------------------------
// TimeAwareKAN via single GEMM  out[m,o] = sum_k F[m,k] * W[o,k] + b[o]
//   M = 49152, K = 768 (6 families x 128), O = 512
// R14: ONE persistent kernel; ticket-ordered phases off a global atomic:
//   tickets [0,96)    : W fp16 pack slices          -> w_done counter
//   tickets [96,480)  : feature m-blocks (128 rows) -> per-block flags
//   tickets [480,2016): GEMM 128x128 tiles (spin on w_done + flag[mb])
// Feature materialization overlaps the GEMM instead of serializing ~29us in
// front of it. GEMM inner pipeline identical to R13 (3-stage cp.async,
// 2 CTAs/SM, 4 warps, 64x64 warp tiles) - it runs at the HMMA rt=8 floor.
// t_indices is int32 on device (JAX x64 disabled).
// ---------------------------------------------------------------------------

#define B_   4
#define H_   24
#define N_   512
#define C_   120
#define D_   128
#define O_   512
#define G_   5
#define M_TOTAL (B_ * H_ * N_)
#define K_TOTAL 768

#define BM 128
#define BN 128
#define KC 64
#define NCHUNK (K_TOTAL / KC)    // 12
#define THREADS 128
#define NSTAGE 3

#define NT_W 96                  // 96 x 4096 = 393216 W elements
#define NT_F (M_TOTAL / BM)      // 384 feature m-blocks
#define NT_G ((M_TOTAL / BM) * (O_ / BN))   // 1536 GEMM tiles
#define T_F0 NT_W
#define T_G0 (NT_W + NT_F)
#define NT_TOTAL (NT_W + NT_F + NT_G)       // 2016
#define NPERSIST 296

#define STAGE_BYTES 32768
#define SMEM_BYTES  (NSTAGE * STAGE_BYTES + 128)

__device__ __half g_W_h[O_ * K_TOTAL];            // 0.75 MB
__device__ __half g_F[(size_t)M_TOTAL * K_TOTAL]; // 75.5 MB scratch
__device__ int    g_ctr;
__device__ int    g_wdone;
__device__ int    g_flags[NT_F];

__global__ void reset_kernel() {
    int i = threadIdx.x;
    if (i == 0) { g_ctr = 0; g_wdone = 0; }
    for (int f = i; f < NT_F; f += blockDim.x) g_flags[f] = 0;
}

// ---------------- helpers ----------------
__device__ __forceinline__ uint32_t s2u(const void* p) {
    uint32_t a;
    asm("{ .reg .u64 t; cvta.to.shared.u64 t, %1; cvt.u32.u64 %0, t; }"
        : "=r"(a) : "l"(p));
    return a;
}
#define SWZ(o) ((o) ^ (((o) >> 3) & 0x70))

__device__ __forceinline__ void ldsm4(uint32_t* r, uint32_t addr) {
    asm volatile("ldmatrix.sync.aligned.m8n8.x4.shared.b16 {%0,%1,%2,%3}, [%4];"
        : "=r"(r[0]), "=r"(r[1]), "=r"(r[2]), "=r"(r[3]) : "r"(addr));
}
__device__ __forceinline__ void mma16816(float* c, const uint32_t* a,
                                         const uint32_t* b) {
    asm volatile(
        "mma.sync.aligned.m16n8k16.row.col.f32.f16.f16.f32 "
        "{%0,%1,%2,%3}, {%4,%5,%6,%7}, {%8,%9}, {%0,%1,%2,%3};"
        : "+f"(c[0]), "+f"(c[1]), "+f"(c[2]), "+f"(c[3])
        : "r"(a[0]), "r"(a[1]), "r"(a[2]), "r"(a[3]), "r"(b[0]), "r"(b[1]));
}

__global__ __launch_bounds__(THREADS, 2)
void kan_persist(const float* __restrict__ base_w,
                 const float* __restrict__ spline_w,
                 const float* __restrict__ x,
                 const int* __restrict__ t_indices,
                 const float* __restrict__ time_emb,
                 const float* __restrict__ base_b,
                 float* __restrict__ out) {
    extern __shared__ char smem[];
    const uint32_t sb = s2u(smem) + 128;
    const int tid = threadIdx.x, wid = tid >> 5, lane = tid & 31;

    const int warp_m = wid & 1;
    const int warp_n = wid >> 1;

    // per-lane ldmatrix address components (SW128)
    const uint32_t kaoff = ((lane >> 4) & 1) * 16;
    uint32_t aB[4], aX[4];
#pragma unroll
    for (int t = 0; t < 4; ++t) {
        int r = warp_m * 64 + t * 16 + ((lane >> 3) & 1) * 8 + (lane & 7);
        aB[t] = r * 128;
        aX[t] = (r & 7) * 16;
    }
    const uint32_t kboff = ((lane >> 3) & 1) * 16;
    uint32_t bB[4], bX[4];
#pragma unroll
    for (int ng = 0; ng < 4; ++ng) {
        int r = warp_n * 64 + ng * 16 + ((lane >> 4) & 1) * 8 + (lane & 7);
        bB[ng] = r * 128;
        bX[ng] = (r & 7) * 16;
    }

    for (;;) {
        if (tid == 0) {
            int t = atomicAdd(&g_ctr, 1);
            *(volatile int*)smem = t;
        }
        __syncthreads();
        const int tk = *(volatile int*)smem;
        __syncthreads();
        if (tk >= NT_TOTAL) break;

        if (tk < NT_W) {
            // ---- W pack slice: 4096 elements, coalesced ----
            const int base = tk * 4096;
#pragma unroll
            for (int s = 0; s < 32; ++s) {
                int idx = base + s * 128 + tid;
                int n = idx / K_TOTAL, k = idx - n * K_TOTAL;
                int j = k >> 7, i = k & 127;
                float w = (j == 0) ? base_w[n * D_ + i]
                                   : spline_w[(n * D_ + i) * G_ + (j - 1)];
                g_W_h[idx] = __float2half(w);
            }
            __threadfence();
            __syncthreads();
            if (tid == 0) atomicAdd(&g_wdone, 1);
            continue;
        }

        if (tk < T_G0) {
            // ---- feature m-block: 128 rows x 96 groups-of-8, coalesced ----
            const int mb = tk - T_F0;
            const int m0 = mb * BM;
            const int h = (m0 >> 9) % H_;
            int ts = t_indices[h];
            ts = min(max(ts, 0), H_ - 1);
            const float* emb8 = time_emb + ts * 8;
#pragma unroll 1
            for (int it = 0; it < 96; ++it) {
                int id = it * 128 + tid;          // < 12288
                int r = id / 96, c8 = id - r * 96;
                int j = c8 >> 4, i0 = (c8 & 15) * 8;
                int m = m0 + r;
                float4 a, b;
                if (i0 < C_) {
                    a = *(const float4*)(x + (size_t)m * C_ + i0);
                    b = *(const float4*)(x + (size_t)m * C_ + i0 + 4);
                } else {
                    a = *(const float4*)(emb8);
                    b = *(const float4*)(emb8 + 4);
                }
                float v[8] = {a.x, a.y, a.z, a.w, b.x, b.y, b.z, b.w};
                float f[8];
                if (j == 0) {
#pragma unroll
                    for (int e = 0; e < 8; ++e)
                        f[e] = __fdividef(v[e], 1.0f + __expf(-v[e]));
                } else {
                    const float gc = -1.0f + 0.5f * (float)(j - 1);
#pragma unroll
                    for (int e = 0; e < 8; ++e) {
                        float t = (v[e] - gc) * 2.0f;
                        f[e] = __expf(-t * t);
                    }
                }
                __half2 h0 = __floats2half2_rn(f[0], f[1]);
                __half2 h1 = __floats2half2_rn(f[2], f[3]);
                __half2 h2 = __floats2half2_rn(f[4], f[5]);
                __half2 h3 = __floats2half2_rn(f[6], f[7]);
                uint4 o;
                o.x = *(uint32_t*)&h0; o.y = *(uint32_t*)&h1;
                o.z = *(uint32_t*)&h2; o.w = *(uint32_t*)&h3;
                *(uint4*)(g_F + (size_t)m * K_TOTAL + j * 128 + i0) = o;
            }
            __threadfence();
            __syncthreads();
            if (tid == 0) atomicExch(&g_flags[mb], 1);
            continue;
        }

        // ---- GEMM tile ----
        const int tile = tk - T_G0;
        const int mb = tile >> 2;
        const int m0 = mb * BM;
        const int o0 = (tile & 3) * BN;

        if (tid == 0) {
            while (atomicAdd(&g_wdone, 0) != NT_W) __nanosleep(128);
            while (atomicAdd(&g_flags[mb], 0) == 0) __nanosleep(128);
        }
        __syncthreads();
        __threadfence();   // acquire: order cp.async reads after flag

        float acc[4][8][4];
#pragma unroll
        for (int t = 0; t < 4; ++t)
#pragma unroll
            for (int j = 0; j < 8; ++j)
#pragma unroll
                for (int e = 0; e < 4; ++e) acc[t][j][e] = 0.0f;

        auto issue_chunk = [&](int kt) {
            const int stage = kt % NSTAGE;
            const int k0 = kt * KC;
            const uint32_t fbase = sb + stage * STAGE_BYTES;
            const uint32_t wbase = fbase + 16384;
#pragma unroll
            for (int s = 0; s < 8; ++s) {
                int v = tid + THREADS * s;
                int r = v >> 3, u = v & 7;
                const __half* src = g_F + (size_t)(m0 + r) * K_TOTAL + k0 + u * 8;
                uint32_t dst = fbase + SWZ((uint32_t)(r * 128 + u * 16));
                asm volatile("cp.async.cg.shared.global [%0], [%1], 16;"
                             :: "r"(dst), "l"(src));
            }
#pragma unroll
            for (int s = 0; s < 8; ++s) {
                int v = tid + THREADS * s;
                int r = v >> 3, u = v & 7;
                const __half* src = g_W_h + (size_t)(o0 + r) * K_TOTAL + k0 + u * 8;
                uint32_t dst = wbase + SWZ((uint32_t)(r * 128 + u * 16));
                asm volatile("cp.async.cg.shared.global [%0], [%1], 16;"
                             :: "r"(dst), "l"(src));
            }
            asm volatile("cp.async.commit_group;" ::: "memory");
        };

        issue_chunk(0);
        issue_chunk(1);
        asm volatile("cp.async.wait_group 1;" ::: "memory");
        __syncthreads();

#pragma unroll 1
        for (int kt = 0; kt < NCHUNK; ++kt) {
            if (kt + 2 < NCHUNK) {
                issue_chunk(kt + 2);
            } else {
                asm volatile("cp.async.commit_group;" ::: "memory");
            }

            const uint32_t fb = sb + (kt % NSTAGE) * STAGE_BYTES;
            const uint32_t wb = fb + 16384;

#pragma unroll
            for (int s = 0; s < 4; ++s) {
                const uint32_t ka = s * 32 + kaoff;
                const uint32_t kb = s * 32 + kboff;
                uint32_t ah[4][4];
#pragma unroll
                for (int t = 0; t < 4; ++t)
                    ldsm4(ah[t], fb + aB[t] + (ka ^ aX[t]));
#pragma unroll
                for (int ng = 0; ng < 4; ++ng) {
                    uint32_t bh[4];
                    ldsm4(bh, wb + bB[ng] + (kb ^ bX[ng]));
#pragma unroll
                    for (int t = 0; t < 4; ++t) {
                        mma16816(acc[t][ng * 2 + 0], ah[t], bh + 0);
                        mma16816(acc[t][ng * 2 + 1], ah[t], bh + 2);
                    }
                }
            }

            asm volatile("cp.async.wait_group 1;" ::: "memory");
            __syncthreads();
        }

        // epilogue
        {
            const float* bb = base_b + o0 + warp_n * 64;
            float2 bi[8];
#pragma unroll
            for (int j = 0; j < 8; ++j)
                bi[j] = *(const float2*)(bb + j * 8 + (lane & 3) * 2);
#pragma unroll
            for (int t = 0; t < 4; ++t) {
                int r0 = m0 + warp_m * 64 + t * 16 + (lane >> 2);
                float* p0 = out + (size_t)r0 * O_ + o0 + warp_n * 64;
                float* p1 = p0 + (size_t)8 * O_;
#pragma unroll
                for (int j = 0; j < 8; ++j) {
                    int col = j * 8 + (lane & 3) * 2;
                    float2 v0, v1;
                    v0.x = acc[t][j][0] + bi[j].x;
                    v0.y = acc[t][j][1] + bi[j].y;
                    v1.x = acc[t][j][2] + bi[j].x;
                    v1.y = acc[t][j][3] + bi[j].y;
                    *(float2*)(p0 + col) = v0;
                    *(float2*)(p1 + col) = v1;
                }
            }
        }
    }
}

extern "C" void kernel_launch(void* const* d_in, const int* in_sizes, int n_in,
                              void* d_out, int out_size) {
    const float* x         = (const float*)d_in[0];
    const int*   t_indices = (const int*)d_in[1];   // int32 (JAX x64 disabled)
    const float* time_emb  = (const float*)d_in[2];
    const float* base_w    = (const float*)d_in[3];
    const float* base_b    = (const float*)d_in[4];
    const float* spline_w  = (const float*)d_in[5];
    float* out = (float*)d_out;

    reset_kernel<<<1, 512>>>();

    cudaFuncSetAttribute(kan_persist,
                         cudaFuncAttributeMaxDynamicSharedMemorySize, SMEM_BYTES);
    kan_persist<<<NPERSIST, THREADS, SMEM_BYTES>>>(base_w, spline_w, x,
                                                   t_indices, time_emb,
                                                   base_b, out);
}

// round 17
// speedup vs baseline: 1.2337x; 1.2337x over previous
#include <cuda_runtime.h>
#include <cuda_fp16.h>
#include <cstdint>

// ---------------------------------------------------------------------------
// TimeAwareKAN via single GEMM  out[m,o] = sum_k F[m,k] * W[o,k] + b[o]
//   M = 49152, K = 768 (6 families x 128), O = 512
// R16: best measured pieces recombined.
//   - separate prep_W (5us, also resets tile counter) + feat kernel (12us)
//     (R14 showed fusing producers into the GEMM kernel costs tensor util)
//   - R13 persistent GEMM (296 CTAs, 2/SM, 3-stage cp.async, 64x64 warp
//     tiles) + CROSS-TILE pipelining: 12 chunks % 3 stages == 0, so the
//     stage map is tile-invariant; at kt=10,11 issue chunks 0,1 of the
//     NEXT ticket instead of empty commit groups -> pipeline never drains.
// t_indices is int32 on device (JAX x64 disabled).
// ---------------------------------------------------------------------------

#define B_   4
#define H_   24
#define N_   512
#define C_   120
#define D_   128
#define O_   512
#define G_   5
#define M_TOTAL (B_ * H_ * N_)
#define K_TOTAL 768

#define BM 128
#define BN 128
#define KC 64
#define NCHUNK (K_TOTAL / KC)    // 12
#define THREADS 128
#define NSTAGE 3
#define NTILES ((M_TOTAL / BM) * (O_ / BN))   // 1536
#define NPERSIST 296

#define STAGE_BYTES 32768
#define SMEM_BYTES  (NSTAGE * STAGE_BYTES + 128)

__device__ __half g_W_h[O_ * K_TOTAL];            // 0.75 MB
__device__ __half g_F[(size_t)M_TOTAL * K_TOTAL]; // 75.5 MB scratch
__device__ int    g_ctr;

__global__ void prep_W(const float* __restrict__ base_w,
                       const float* __restrict__ spline_w) {
    if (blockIdx.x == 0 && threadIdx.x == 0) g_ctr = 0;   // reset tile counter
    int idx = blockIdx.x * blockDim.x + threadIdx.x;
    if (idx >= O_ * K_TOTAL) return;
    int n = idx / K_TOTAL, k = idx - n * K_TOTAL;
    int j = k >> 7, i = k & 127;
    float w = (j == 0) ? base_w[n * D_ + i]
                       : spline_w[(n * D_ + i) * G_ + (j - 1)];
    g_W_h[idx] = __float2half(w);
}

// ---- Feature kernel: one thread -> 8 contiguous k of one row ----
__global__ __launch_bounds__(512)
void feat_kernel(const float* __restrict__ x,
                 const int* __restrict__ t_indices,
                 const float* __restrict__ time_emb) {
    int g = blockIdx.x * 512 + threadIdx.x;        // < M*96
    int m = g / 96, c8 = g - m * 96;
    int j = c8 >> 4, i0 = (c8 & 15) * 8;

    float4 a, b;
    if (i0 < C_) {
        a = *(const float4*)(x + (size_t)m * C_ + i0);
        b = *(const float4*)(x + (size_t)m * C_ + i0 + 4);
    } else {                                       // i0 == 120: time emb
        int h = (m >> 9) % H_;
        int ts = t_indices[h];
        ts = min(max(ts, 0), H_ - 1);
        a = *(const float4*)(time_emb + ts * 8);
        b = *(const float4*)(time_emb + ts * 8 + 4);
    }
    float v[8] = {a.x, a.y, a.z, a.w, b.x, b.y, b.z, b.w};
    float f[8];
    if (j == 0) {
#pragma unroll
        for (int e = 0; e < 8; ++e)
            f[e] = __fdividef(v[e], 1.0f + __expf(-v[e]));
    } else {
        const float gc = -1.0f + 0.5f * (float)(j - 1);
#pragma unroll
        for (int e = 0; e < 8; ++e) {
            float t = (v[e] - gc) * 2.0f;
            f[e] = __expf(-t * t);
        }
    }
    __half2 h0 = __floats2half2_rn(f[0], f[1]);
    __half2 h1 = __floats2half2_rn(f[2], f[3]);
    __half2 h2 = __floats2half2_rn(f[4], f[5]);
    __half2 h3 = __floats2half2_rn(f[6], f[7]);
    uint4 o;
    o.x = *(uint32_t*)&h0; o.y = *(uint32_t*)&h1;
    o.z = *(uint32_t*)&h2; o.w = *(uint32_t*)&h3;
    *(uint4*)(g_F + (size_t)m * K_TOTAL + j * 128 + i0) = o;
}

// ---------------- helpers ----------------
__device__ __forceinline__ uint32_t s2u(const void* p) {
    uint32_t a;
    asm("{ .reg .u64 t; cvta.to.shared.u64 t, %1; cvt.u32.u64 %0, t; }"
        : "=r"(a) : "l"(p));
    return a;
}
#define SWZ(o) ((o) ^ (((o) >> 3) & 0x70))

__device__ __forceinline__ void ldsm4(uint32_t* r, uint32_t addr) {
    asm volatile("ldmatrix.sync.aligned.m8n8.x4.shared.b16 {%0,%1,%2,%3}, [%4];"
        : "=r"(r[0]), "=r"(r[1]), "=r"(r[2]), "=r"(r[3]) : "r"(addr));
}
__device__ __forceinline__ void mma16816(float* c, const uint32_t* a,
                                         const uint32_t* b) {
    asm volatile(
        "mma.sync.aligned.m16n8k16.row.col.f32.f16.f16.f32 "
        "{%0,%1,%2,%3}, {%4,%5,%6,%7}, {%8,%9}, {%0,%1,%2,%3};"
        : "+f"(c[0]), "+f"(c[1]), "+f"(c[2]), "+f"(c[3])
        : "r"(a[0]), "r"(a[1]), "r"(a[2]), "r"(a[3]), "r"(b[0]), "r"(b[1]));
}

__global__ __launch_bounds__(THREADS, 2)
void kan_hmma_kernel(const float* __restrict__ base_b,
                     float* __restrict__ out) {
    extern __shared__ char smem[];
    const uint32_t sb = s2u(smem) + 128;     // stages after broadcast slot
    const int tid = threadIdx.x, wid = tid >> 5, lane = tid & 31;

    const int warp_m = wid & 1;
    const int warp_n = wid >> 1;

    // per-lane ldmatrix address components (SW128)
    const uint32_t kaoff = ((lane >> 4) & 1) * 16;
    uint32_t aB[4], aX[4];
#pragma unroll
    for (int t = 0; t < 4; ++t) {
        int r = warp_m * 64 + t * 16 + ((lane >> 3) & 1) * 8 + (lane & 7);
        aB[t] = r * 128;
        aX[t] = (r & 7) * 16;
    }
    const uint32_t kboff = ((lane >> 3) & 1) * 16;
    uint32_t bB[4], bX[4];
#pragma unroll
    for (int ng = 0; ng < 4; ++ng) {
        int r = warp_n * 64 + ng * 16 + ((lane >> 4) & 1) * 8 + (lane & 7);
        bB[ng] = r * 128;
        bX[ng] = (r & 7) * 16;
    }

    // issue chunk c (stage c%3 -- tile-invariant since NCHUNK%NSTAGE==0)
    auto issue_chunk = [&](int m0, int o0, int c) {
        const uint32_t fbase = sb + (c % NSTAGE) * STAGE_BYTES;
        const uint32_t wbase = fbase + 16384;
        const int k0 = c * KC;
#pragma unroll
        for (int s = 0; s < 8; ++s) {
            int v = tid + THREADS * s;
            int r = v >> 3, u = v & 7;
            const __half* src = g_F + (size_t)(m0 + r) * K_TOTAL + k0 + u * 8;
            uint32_t dst = fbase + SWZ((uint32_t)(r * 128 + u * 16));
            asm volatile("cp.async.cg.shared.global [%0], [%1], 16;"
                         :: "r"(dst), "l"(src));
        }
#pragma unroll
        for (int s = 0; s < 8; ++s) {
            int v = tid + THREADS * s;
            int r = v >> 3, u = v & 7;
            const __half* src = g_W_h + (size_t)(o0 + r) * K_TOTAL + k0 + u * 8;
            uint32_t dst = wbase + SWZ((uint32_t)(r * 128 + u * 16));
            asm volatile("cp.async.cg.shared.global [%0], [%1], 16;"
                         :: "r"(dst), "l"(src));
        }
        asm volatile("cp.async.commit_group;" ::: "memory");
    };

    // ---- first ticket + prologue ----
    if (tid == 0) *(volatile int*)smem = atomicAdd(&g_ctr, 1);
    __syncthreads();
    int tile_cur = *(volatile int*)smem;
    __syncthreads();
    if (tile_cur >= NTILES) return;       // not possible with 296 <= 1536

    {
        const int m0 = (tile_cur >> 2) * BM, o0 = (tile_cur & 3) * BN;
        issue_chunk(m0, o0, 0);
        issue_chunk(m0, o0, 1);
    }
    asm volatile("cp.async.wait_group 1;" ::: "memory");
    __syncthreads();

    // ---- persistent tile loop (pipeline never drains) ----
    for (;;) {
        const int m0 = (tile_cur >> 2) * BM;
        const int o0 = (tile_cur & 3) * BN;

        // prefetch next ticket into broadcast slot (read at kt>=10; ordered
        // by the chunk-loop __syncthreads between write and reads)
        if (tid == 0) *(volatile int*)smem = atomicAdd(&g_ctr, 1);

        float acc[4][8][4];
#pragma unroll
        for (int t = 0; t < 4; ++t)
#pragma unroll
            for (int j = 0; j < 8; ++j)
#pragma unroll
                for (int e = 0; e < 4; ++e) acc[t][j][e] = 0.0f;

        int tile_next = NTILES;

#pragma unroll 1
        for (int kt = 0; kt < NCHUNK; ++kt) {
            if (kt + 2 < NCHUNK) {
                issue_chunk(m0, o0, kt + 2);
            } else {
                // kt = 10, 11: issue chunks 0,1 of the next tile
                tile_next = *(volatile int*)smem;
                if (tile_next < NTILES) {
                    issue_chunk((tile_next >> 2) * BM, (tile_next & 3) * BN,
                                kt + 2 - NCHUNK);
                } else {
                    asm volatile("cp.async.commit_group;" ::: "memory");
                }
            }

            const uint32_t fb = sb + (kt % NSTAGE) * STAGE_BYTES;
            const uint32_t wb = fb + 16384;

#pragma unroll
            for (int s = 0; s < 4; ++s) {
                const uint32_t ka = s * 32 + kaoff;
                const uint32_t kb = s * 32 + kboff;
                uint32_t ah[4][4];
#pragma unroll
                for (int t = 0; t < 4; ++t)
                    ldsm4(ah[t], fb + aB[t] + (ka ^ aX[t]));
#pragma unroll
                for (int ng = 0; ng < 4; ++ng) {
                    uint32_t bh[4];
                    ldsm4(bh, wb + bB[ng] + (kb ^ bX[ng]));
#pragma unroll
                    for (int t = 0; t < 4; ++t) {
                        mma16816(acc[t][ng * 2 + 0], ah[t], bh + 0);
                        mma16816(acc[t][ng * 2 + 1], ah[t], bh + 2);
                    }
                }
            }

            asm volatile("cp.async.wait_group 1;" ::: "memory");
            __syncthreads();
        }

        // ---- epilogue (regs only; next tile's loads already in flight) ----
        {
            const float* bb = base_b + o0 + warp_n * 64;
            float2 bi[8];
#pragma unroll
            for (int j = 0; j < 8; ++j)
                bi[j] = *(const float2*)(bb + j * 8 + (lane & 3) * 2);
#pragma unroll
            for (int t = 0; t < 4; ++t) {
                int r0 = m0 + warp_m * 64 + t * 16 + (lane >> 2);
                float* p0 = out + (size_t)r0 * O_ + o0 + warp_n * 64;
                float* p1 = p0 + (size_t)8 * O_;
#pragma unroll
                for (int j = 0; j < 8; ++j) {
                    int col = j * 8 + (lane & 3) * 2;
                    float2 v0, v1;
                    v0.x = acc[t][j][0] + bi[j].x;
                    v0.y = acc[t][j][1] + bi[j].y;
                    v1.x = acc[t][j][2] + bi[j].x;
                    v1.y = acc[t][j][3] + bi[j].y;
                    *(float2*)(p0 + col) = v0;
                    *(float2*)(p1 + col) = v1;
                }
            }
        }

        if (tile_next >= NTILES) break;
        tile_cur = tile_next;
    }
}

extern "C" void kernel_launch(void* const* d_in, const int* in_sizes, int n_in,
                              void* d_out, int out_size) {
    const float* x         = (const float*)d_in[0];
    const int*   t_indices = (const int*)d_in[1];   // int32 (JAX x64 disabled)
    const float* time_emb  = (const float*)d_in[2];
    const float* base_w    = (const float*)d_in[3];
    const float* base_b    = (const float*)d_in[4];
    const float* spline_w  = (const float*)d_in[5];
    float* out = (float*)d_out;

    {
        int total = O_ * K_TOTAL;
        prep_W<<<(total + 255) / 256, 256>>>(base_w, spline_w);
    }
    feat_kernel<<<(M_TOTAL * 96) / 512, 512>>>(x, t_indices, time_emb);

    cudaFuncSetAttribute(kan_hmma_kernel,
                         cudaFuncAttributeMaxDynamicSharedMemorySize, SMEM_BYTES);
    kan_hmma_kernel<<<NPERSIST, THREADS, SMEM_BYTES>>>(base_b, out);
}